// round 5
// baseline (speedup 1.0000x reference)
#include <cuda_runtime.h>
#include <math.h>
#include <stdint.h>

#define Nn 4096
#define Lt 256
#define TLt 128
#define MUc 0.001f
#define Ac 0.999f          /* 1-mu */
#define NM1 4095.0f
#define INV_NM1 (1.0f/4095.0f)
#define EPSF 2.2204460492503131e-16f
#define NNsz ((size_t)Nn*(size_t)Nn)

typedef unsigned long long ull;

// ---- scratch (device globals; no allocations allowed) ----
__device__ uint32_t g_pk[Lt * 128];     // h packed to bits: [L][128] words
__device__ float    g_rho[Lt];
__device__ float    g_alpha_fb[NNsz];   // fallbacks if out buffer too small
__device__ float    g_beta_fb[NNsz];

// ---- packed f32x2 helpers ----
__device__ __forceinline__ ull pk2(float lo, float hi) {
    ull r; asm("mov.b64 %0,{%1,%2};" : "=l"(r) : "f"(lo), "f"(hi)); return r;
}
__device__ __forceinline__ void up2(ull v, float& lo, float& hi) {
    asm("mov.b64 {%0,%1},%2;" : "=f"(lo), "=f"(hi) : "l"(v));
}
__device__ __forceinline__ ull ffma2(ull a, ull b, ull c) {
    ull d; asm("fma.rn.f32x2 %0,%1,%2,%3;" : "=l"(d) : "l"(a), "l"(b), "l"(c)); return d;
}
__device__ __forceinline__ ull fmul2(ull a, ull b) {
    ull d; asm("mul.rn.f32x2 %0,%1,%2;" : "=l"(d) : "l"(a), "l"(b)); return d;
}
__device__ __forceinline__ ull fadd2(ull a, ull b) {
    ull d; asm("add.rn.f32x2 %0,%1,%2;" : "=l"(d) : "l"(a), "l"(b)); return d;
}
__device__ __forceinline__ float frcp_fast(float x) {
    float r; asm("rcp.approx.f32 %0,%1;" : "=f"(r) : "f"(x)); return r;
}

// rho[l] = -expm1(-n_e * m[l]),  n_e = 4*10000/4096 = 9.765625
__global__ void k_rho(float* __restrict__ rho, const float* __restrict__ m) {
    int t = threadIdx.x;
    if (t < Lt) rho[t] = -expm1f(-9.765625f * m[t]);
}

// pack h rows into bitmasks
__global__ void k_pack(const int* __restrict__ h, uint32_t* __restrict__ pk) {
    const int l = blockIdx.x;
    const int w = threadIdx.x;           // 0..127
    const int* row = h + (size_t)l * Nn + w * 32;
    uint32_t v = 0;
#pragma unroll
    for (int b = 0; b < 32; ++b) v |= ((uint32_t)(row[b] & 1)) << b;
    pk[l * 128 + w] = v;
}

// ---- one-barrier block sum of 4 partials; TOTALS returned in registers of
// every thread. swarp is double-buffered [2][16] indexed by parity. 512 thr.
__device__ __forceinline__ float4 blockSum4(float s0, float s1, float s2, float s3,
                                            float4* swarp, int t, int par) {
#pragma unroll
    for (int off = 16; off; off >>= 1) {
        s0 += __shfl_xor_sync(0xFFFFFFFFu, s0, off);
        s1 += __shfl_xor_sync(0xFFFFFFFFu, s1, off);
        s2 += __shfl_xor_sync(0xFFFFFFFFu, s2, off);
        s3 += __shfl_xor_sync(0xFFFFFFFFu, s3, off);
    }
    float4* buf = swarp + (par << 4);
    if ((t & 31) == 0) buf[t >> 5] = make_float4(s0, s1, s2, s3);
    __syncthreads();
    float4 v = buf[t & 15];
#pragma unroll
    for (int off = 8; off; off >>= 1) {
        v.x += __shfl_xor_sync(0xFFFFFFFFu, v.x, off, 16);
        v.y += __shfl_xor_sync(0xFFFFFFFFu, v.y, off, 16);
        v.z += __shfl_xor_sync(0xFFFFFFFFu, v.z, off, 16);
        v.w += __shfl_xor_sync(0xFFFFFFFFu, v.w, off, 16);
    }
    return v;
}

// diag fix (fwd): subtract diag values from packed sums AND zero state lanes.
__device__ __forceinline__ void diag_fix_fwd(ull& a0, ull& a1, ull& b2, ull& b3,
                                             ull& s0, ull& s1) {
    float lo, hi, sl, sh;
    up2(s0, sl, sh);
    up2(a0, lo, hi); sl -= lo; a0 = pk2(0.f, hi);
    up2(a1, lo, hi); sh -= hi; a1 = pk2(lo, 0.f);
    s0 = pk2(sl, sh);
    up2(s1, sl, sh);
    up2(b2, lo, hi); sl -= lo; b2 = pk2(0.f, hi);
    up2(b3, lo, hi); sh -= hi; b3 = pk2(lo, 0.f);
    s1 = pk2(sl, sh);
}
__device__ __forceinline__ void diag_sub(const ull a0, const ull a1, const ull b2,
                                         const ull b3, ull& s0, ull& s1) {
    float lo, hi, sl, sh;
    up2(s0, sl, sh);
    up2(a0, lo, hi); sl -= lo;
    up2(a1, lo, hi); sh -= hi;
    s0 = pk2(sl, sh);
    up2(s1, sl, sh);
    up2(b2, lo, hi); sl -= lo;
    up2(b3, lo, hi); sh -= hi;
    s1 = pk2(sl, sh);
}
__device__ __forceinline__ void diag_zero(ull& a0, ull& a1, ull& b2, ull& b3) {
    a0 &= 0xFFFFFFFF00000000ull;  // zero lo lane
    a1 &= 0x00000000FFFFFFFFull;  // zero hi lane
    b2 &= 0xFFFFFFFF00000000ull;
    b3 &= 0x00000000FFFFFFFFull;
}

// ---------------- forward body: 129 steps resident in registers ----------------
__device__ __forceinline__ void fwd_body(float* __restrict__ alphaOut, int blk,
                                         float4* swarp, float* srho) {
    const int t = threadIdx.x;
    const int j0 = blk << 2;
    const int r0 = t << 3;
    if (t < Lt) srho[t] = g_rho[t];

    ull st[8][2];
#pragma unroll
    for (int r = 0; r < 8; ++r) { st[r][0] = 0ull; st[r][1] = 0ull; }
    float4 tot = make_float4(1.f, 1.f, 1.f, 1.f);   // dummy; step0 uses w=0
    __syncthreads();

    const int wWord = r0 >> 5, wSh = r0 & 31;
    const int jWord = j0 >> 5, jSh = j0 & 31;
    const bool isDiagT = (t == (j0 >> 3));
    const bool diagHi = (j0 & 7) != 0;   // diag rows 4..7 vs 0..3

    for (int step = 0; step <= TLt; ++step) {
        const uint32_t* row = g_pk + step * 128;
        const uint32_t hb = __ldg(row + wWord) >> wSh;
        const uint32_t hj = (__ldg(row + jWord) >> jSh) & 0xFu;

        float wv, cst;
        if (step == 0) { wv = 0.0f; cst = INV_NM1; }
        else { const float r = srho[step - 1]; wv = 1.0f - r; cst = r * INV_NM1; }

        const float e0a = (hj & 1u) ? MUc : Ac, e1a = (hj & 1u) ? Ac : MUc;
        const float e0b = (hj & 2u) ? MUc : Ac, e1b = (hj & 2u) ? Ac : MUc;
        const float e0c = (hj & 4u) ? MUc : Ac, e1c = (hj & 4u) ? Ac : MUc;
        const float e0d = (hj & 8u) ? MUc : Ac, e1d = (hj & 8u) ? Ac : MUc;
        const ull E0p0 = pk2(e0a, e0b), E1p0 = pk2(e1a, e1b);
        const ull E0p1 = pk2(e0c, e0d), E1p1 = pk2(e1c, e1d);
        const ull wp0 = pk2(wv * frcp_fast(tot.x), wv * frcp_fast(tot.y));
        const ull wp1 = pk2(wv * frcp_fast(tot.z), wv * frcp_fast(tot.w));
        const ull cstp = pk2(cst, cst);

        ull sm0 = 0ull, sm1 = 0ull;
#pragma unroll
        for (int r = 0; r < 8; ++r) {
            const bool hi = (hb >> r) & 1u;
            const ull ea = hi ? E1p0 : E0p0;
            const ull eb = hi ? E1p1 : E0p1;
            const ull o0 = fmul2(ffma2(st[r][0], wp0, cstp), ea);
            const ull o1 = fmul2(ffma2(st[r][1], wp1, cstp), eb);
            st[r][0] = o0; st[r][1] = o1;
            sm0 = fadd2(sm0, o0); sm1 = fadd2(sm1, o1);
        }
        if (isDiagT) {
            if (diagHi) diag_fix_fwd(st[4][0], st[5][0], st[6][1], st[7][1], sm0, sm1);
            else        diag_fix_fwd(st[0][0], st[1][0], st[2][1], st[3][1], sm0, sm1);
        }
        if (step < TLt) {
            float a0, a1, a2, a3;
            up2(sm0, a0, a1); up2(sm1, a2, a3);
            tot = blockSum4(a0, a1, a2, a3, swarp, t, step & 1);
        }
    }
#pragma unroll
    for (int r = 0; r < 8; ++r) {
        float x, y, z, w;
        up2(st[r][0], x, y); up2(st[r][1], z, w);
        *(float4*)(alphaOut + (size_t)(r0 + r) * Nn + j0) = make_float4(x, y, z, w);
    }
}

// ---------------- backward body: 127 steps resident ----------------
__device__ __forceinline__ void bwd_body(float* __restrict__ betaOut, int blk,
                                         float4* swarp, float* srho) {
    const int t = threadIdx.x;
    const int j0 = blk << 2;
    const int r0 = t << 3;
    if (t < Lt) srho[t] = g_rho[t];

    ull st[8][2];
    const ull one2 = pk2(1.0f, 1.0f);
#pragma unroll
    for (int r = 0; r < 8; ++r) { st[r][0] = one2; st[r][1] = one2; }
    __syncthreads();

    const int wWord = r0 >> 5, wSh = r0 & 31;
    const int jWord = j0 >> 5, jSh = j0 & 31;
    const bool isDiagT = (t == (j0 >> 3));
    const bool diagHi = (j0 & 7) != 0;

    for (int k = 0; k < Lt - 1 - TLt; ++k) {
        const int lr = Lt - 1 - k;                 // h row index l+1
        const uint32_t* row = g_pk + lr * 128;
        const uint32_t hb = __ldg(row + wWord) >> wSh;
        const uint32_t hj = (__ldg(row + jWord) >> jSh) & 0xFu;
        const float rr = srho[Lt - 2 - k];

        const float e0a = (hj & 1u) ? MUc : Ac, e1a = (hj & 1u) ? Ac : MUc;
        const float e0b = (hj & 2u) ? MUc : Ac, e1b = (hj & 2u) ? Ac : MUc;
        const float e0c = (hj & 4u) ? MUc : Ac, e1c = (hj & 4u) ? Ac : MUc;
        const float e0d = (hj & 8u) ? MUc : Ac, e1d = (hj & 8u) ? Ac : MUc;
        const ull E0p0 = pk2(e0a, e0b), E1p0 = pk2(e1a, e1b);
        const ull E0p1 = pk2(e0c, e0d), E1p1 = pk2(e1c, e1d);

        // phase A: b = theta * beta, accumulate column sums
        ull sm0 = 0ull, sm1 = 0ull;
#pragma unroll
        for (int r = 0; r < 8; ++r) {
            const bool hi = (hb >> r) & 1u;
            const ull ea = hi ? E1p0 : E0p0;
            const ull eb = hi ? E1p1 : E0p1;
            const ull b0 = fmul2(st[r][0], ea);
            const ull b1 = fmul2(st[r][1], eb);
            st[r][0] = b0; st[r][1] = b1;
            sm0 = fadd2(sm0, b0); sm1 = fadd2(sm1, b1);
        }
        if (isDiagT) {
            if (diagHi) diag_sub(st[4][0], st[5][0], st[6][1], st[7][1], sm0, sm1);
            else        diag_sub(st[0][0], st[1][0], st[2][1], st[3][1], sm0, sm1);
        }
        float a0, a1, a2, a3;
        up2(sm0, a0, a1); up2(sm1, a2, a3);
        const float4 tot = blockSum4(a0, a1, a2, a3, swarp, t, k & 1);

        // phase B: beta = (1-r)*b*(n-1)/sum + r; zero diagonal
        const float kscale = (1.0f - rr) * NM1;
        const ull kp0 = pk2(kscale * frcp_fast(tot.x), kscale * frcp_fast(tot.y));
        const ull kp1 = pk2(kscale * frcp_fast(tot.z), kscale * frcp_fast(tot.w));
        const ull rp = pk2(rr, rr);
#pragma unroll
        for (int r = 0; r < 8; ++r) {
            st[r][0] = ffma2(st[r][0], kp0, rp);
            st[r][1] = ffma2(st[r][1], kp1, rp);
        }
        if (isDiagT) {
            if (diagHi) diag_zero(st[4][0], st[5][0], st[6][1], st[7][1]);
            else        diag_zero(st[0][0], st[1][0], st[2][1], st[3][1]);
        }
    }
#pragma unroll
    for (int r = 0; r < 8; ++r) {
        float x, y, z, w;
        up2(st[r][0], x, y); up2(st[r][1], z, w);
        *(float4*)(betaOut + (size_t)(r0 + r) * Nn + j0) = make_float4(x, y, z, w);
    }
}

// merged: blocks [0,1024) run forward, [1024,2048) run backward
__global__ void __launch_bounds__(512, 2) k_main(float* __restrict__ alphaOut,
                                                 float* __restrict__ betaOut) {
    __shared__ float4 swarp[32];   // double-buffered: [2][16]
    __shared__ float srho[Lt];
    if (blockIdx.x < 1024) fwd_body(alphaOut, blockIdx.x, swarp, srho);
    else                   bwd_body(betaOut, blockIdx.x - 1024, swarp, srho);
}

// posterior: p = clip01(alpha)*clip01(beta), column-normalized.
// No register cache: reload after reduction (block working set 128KB -> L1-hot).
__global__ void __launch_bounds__(512, 4) k_post(const float* __restrict__ a,
                                                 const float* __restrict__ b,
                                                 float* __restrict__ pOut) {
    __shared__ float4 swarp[32];
    const int t = threadIdx.x;
    const int j0 = blockIdx.x << 2;
    const int r0 = t << 3;
    float s0 = 0, s1 = 0, s2 = 0, s3 = 0;
#pragma unroll
    for (int r = 0; r < 8; ++r) {
        const size_t off = (size_t)(r0 + r) * Nn + j0;
        const float4 av = __ldg((const float4*)(a + off));
        const float4 bv = __ldg((const float4*)(b + off));
        s0 += __saturatef(av.x) * __saturatef(bv.x);
        s1 += __saturatef(av.y) * __saturatef(bv.y);
        s2 += __saturatef(av.z) * __saturatef(bv.z);
        s3 += __saturatef(av.w) * __saturatef(bv.w);
    }
    const float4 tot = blockSum4(s0, s1, s2, s3, swarp, t, 0);
    const float i0 = 1.0f / tot.x, i1 = 1.0f / tot.y;
    const float i2 = 1.0f / tot.z, i3 = 1.0f / tot.w;
#pragma unroll
    for (int r = 0; r < 8; ++r) {
        const size_t off = (size_t)(r0 + r) * Nn + j0;
        const float4 av = __ldg((const float4*)(a + off));
        const float4 bv = __ldg((const float4*)(b + off));
        float4 pv;
        pv.x = __saturatef(av.x) * __saturatef(bv.x) * i0;
        pv.y = __saturatef(av.y) * __saturatef(bv.y) * i1;
        pv.z = __saturatef(av.z) * __saturatef(bv.z) * i2;
        pv.w = __saturatef(av.w) * __saturatef(bv.w) * i3;
        *(float4*)(pOut + off) = pv;
    }
}

// d = -0.5*(log pc + log pc^T)*offdiag; p already normalized; paired 32x32 tiles
__global__ void k_dist(const float* __restrict__ p, float* __restrict__ dOut) {
    const int bi = blockIdx.y, bj = blockIdx.x;
    if (bj < bi) return;
    __shared__ float lA[32][33];
    __shared__ float lB[32][33];
    const int tx = threadIdx.x & 31;
    const int ty0 = threadIdx.x >> 5;  // 0..7
    const int colA = (bj << 5) + tx;
    const int colB = (bi << 5) + tx;
    const bool diagBlk = (bi == bj);
#pragma unroll
    for (int k2 = 0; k2 < 4; ++k2) {
        const int y = ty0 + (k2 << 3);
        const int iA = (bi << 5) + y;
        lA[y][tx] = logf(fmaxf(p[(size_t)iA * Nn + colA], EPSF));
        if (!diagBlk) {
            const int iB = (bj << 5) + y;
            lB[y][tx] = logf(fmaxf(p[(size_t)iB * Nn + colB], EPSF));
        }
    }
    __syncthreads();
    float (*lBr)[33] = diagBlk ? lA : lB;
#pragma unroll
    for (int k2 = 0; k2 < 4; ++k2) {
        const int y = ty0 + (k2 << 3);
        const int iA = (bi << 5) + y;
        float dv = (iA == colA) ? 0.f : -0.5f * (lA[y][tx] + lBr[tx][y]);
        dOut[(size_t)iA * Nn + colA] = dv;
        if (!diagBlk) {
            const int iB = (bj << 5) + y;
            dOut[(size_t)iB * Nn + colB] = -0.5f * (lB[y][tx] + lA[tx][y]);
        }
    }
}

extern "C" void kernel_launch(void* const* d_in, const int* in_sizes, int n_in,
                              void* d_out, int out_size) {
    const int* h = (const int*)d_in[0];
    const float* m = (const float*)d_in[1];
    float* out = (float*)d_out;

    void* sym;
    uint32_t* pk; float *rho, *afb, *bfb;
    cudaGetSymbolAddress(&sym, g_pk);       pk  = (uint32_t*)sym;
    cudaGetSymbolAddress(&sym, g_rho);      rho = (float*)sym;
    cudaGetSymbolAddress(&sym, g_alpha_fb); afb = (float*)sym;
    cudaGetSymbolAddress(&sym, g_beta_fb);  bfb = (float*)sym;

    float *pOut, *dOut, *alphaPtr, *betaPtr;
    size_t osz = (size_t)out_size;
    if (osz >= 4 * NNsz) {
        pOut = out; dOut = out + NNsz; alphaPtr = out + 2 * NNsz; betaPtr = out + 3 * NNsz;
    } else if (osz >= 2 * NNsz) {
        pOut = out; dOut = out + NNsz; alphaPtr = afb; betaPtr = bfb;
    } else {
        pOut = out; dOut = nullptr; alphaPtr = afb; betaPtr = bfb;
    }

    k_rho<<<1, 256>>>(rho, m);
    k_pack<<<Lt, 128>>>(h, pk);
    k_main<<<2048, 512>>>(alphaPtr, betaPtr);
    k_post<<<Nn / 4, 512>>>(alphaPtr, betaPtr, pOut);
    if (dOut != nullptr) {
        dim3 g2(Nn / 32, Nn / 32);
        k_dist<<<g2, 256>>>(pOut, dOut);
    }
}